// round 1
// baseline (speedup 1.0000x reference)
#include <cuda_runtime.h>
#include <cstdint>
#include <cmath>

#define CB 8192          // batch
#define NNODES 25
// group sizes: 25, 9, 7, 6, 6

__constant__ int GIDX[5][25] = {
  {0,1,2,3,4,5,6,7,8,9,10,11,12,13,14,15,16,17,18,19,20,21,22,23,24},
  {0,1,2,3,4,5,6,7,8, 0,0,0,0,0,0,0,0,0,0,0,0,0,0,0,0},
  {0,9,10,11,12,13,14, 0,0,0,0,0,0,0,0,0,0,0,0,0,0,0,0,0,0},
  {6,7,8,12,13,14, 0,0,0,0,0,0,0,0,0,0,0,0,0,0,0,0,0,0,0},
  {3,4,5,9,10,11, 0,0,0,0,0,0,0,0,0,0,0,0,0,0,0,0,0,0,0}
};

// h scratch: sum of group node counts = 53 -> 8192*53*512 floats (~889 MB)
__device__ float g_h[(size_t)CB * 53 * 512];

__host__ __device__ constexpr size_t hpre(int g) {
    return g == 0 ? 0 : g == 1 ? 25 : g == 2 ? 34 : g == 3 ? 41 : 47;
}

// ---------------------------------------------------------------------------
// Fused GCN layer kernel.
//  L2=false: support = x_g @ W1  -> h = relu(NA @ support + b1) -> g_h
//  L2=true : support = h   @ W2  -> out = relu(NA @ support + b2) * nw[g]
//            G==0 stores '=', G>0 does deterministic read-modify-write '+='
// CTA tile: MROWS = BB*GN rows (whole batches, <=128) x 128 cols, K streamed.
// ---------------------------------------------------------------------------
template<int G, int GN, int BB, bool L2>
__global__ __launch_bounds__(256, 2)
void gcn_kernel(const float* __restrict__ x,
                const float* __restrict__ adj,
                const float* __restrict__ W1,
                const float* __restrict__ b1,
                const float* __restrict__ W2,
                const float* __restrict__ b2,
                const float* __restrict__ fw,
                float* __restrict__ dout)
{
    constexpr int K     = L2 ? 512 : 256;   // reduction dim
    constexpr int NW    = L2 ? 256 : 512;   // full width of W (row stride)
    constexpr int KT    = 16;
    constexpr int NK    = K / KT;
    constexpr int MROWS = BB * GN;

    extern __shared__ float smem[];
    float* sA = smem;               // [KT][128]  (k-major, transposed A tile)
    float* sB = smem + KT * 128;    // [KT][128]

    const int tid = threadIdx.x;
    const int tx  = tid & 15;
    const int ty  = tid >> 4;
    const int batch0 = blockIdx.x * BB;
    const int n0 = blockIdx.y * 128;

    float* hreg = g_h + hpre(G) * (size_t)CB * 512;

    const float* Asrc;
    const float* Wsrc;
    const float* bias;
    if (L2) { Asrc = hreg; Wsrc = W2 + (size_t)G * 512 * 256; bias = b2 + G * 256; }
    else    { Asrc = x;    Wsrc = W1 + (size_t)G * 256 * 512; bias = b1 + G * 512; }

    // ---- A-load addressing: 2 float4 per thread per k-tile ----
    const int ar0 = tid >> 2;        // row 0..63
    const int ar1 = ar0 + 64;        // row 64..127
    const int kq  = (tid & 3) * 4;   // k offset within tile
    size_t abase0 = 0, abase1 = 0;
    bool av0, av1;
    {
        const int bb0 = batch0 + ar0 / GN;
        const int bb1 = batch0 + ar1 / GN;
        av0 = (ar0 < MROWS) && (bb0 < CB);
        av1 = (ar1 < MROWS) && (bb1 < CB);
        if (L2) {
            abase0 = (size_t)(batch0 * GN + ar0) * 512;
            abase1 = (size_t)(batch0 * GN + ar1) * 512;
        } else {
            abase0 = ((size_t)bb0 * NNODES + GIDX[G][ar0 % GN]) * 256;
            abase1 = ((size_t)bb1 * NNODES + GIDX[G][ar1 % GN]) * 256;
        }
    }
    // ---- W-load addressing ----
    const int bkr = tid >> 5;          // 0..7
    const int bc  = (tid & 31) * 4;    // 0..124

    uint64_t acc[8][4];                // 8 rows x 8 cols as f32x2 pairs
#pragma unroll
    for (int i = 0; i < 8; ++i)
#pragma unroll
        for (int p = 0; p < 4; ++p) acc[i][p] = 0ull;

    float4 a0v, a1v, b0v, b1v;
    const float4 z4 = make_float4(0.f, 0.f, 0.f, 0.f);

    // prologue: load k-tile 0
    {
        const int k0 = 0;
        a0v = av0 ? *(const float4*)(Asrc + abase0 + k0 + kq) : z4;
        a1v = av1 ? *(const float4*)(Asrc + abase1 + k0 + kq) : z4;
        b0v = *(const float4*)(Wsrc + (size_t)(k0 + bkr) * NW + n0 + bc);
        b1v = *(const float4*)(Wsrc + (size_t)(k0 + bkr + 8) * NW + n0 + bc);
    }

    for (int kt = 0; kt < NK; ++kt) {
        // stage current tile to smem
        sA[(kq + 0) * 128 + ar0] = a0v.x;
        sA[(kq + 1) * 128 + ar0] = a0v.y;
        sA[(kq + 2) * 128 + ar0] = a0v.z;
        sA[(kq + 3) * 128 + ar0] = a0v.w;
        sA[(kq + 0) * 128 + ar1] = a1v.x;
        sA[(kq + 1) * 128 + ar1] = a1v.y;
        sA[(kq + 2) * 128 + ar1] = a1v.z;
        sA[(kq + 3) * 128 + ar1] = a1v.w;
        *(float4*)&sB[bkr * 128 + bc]       = b0v;
        *(float4*)&sB[(bkr + 8) * 128 + bc] = b1v;
        __syncthreads();

        // prefetch next tile into regs (latency hidden under compute)
        if (kt + 1 < NK) {
            const int k0 = (kt + 1) * KT;
            a0v = av0 ? *(const float4*)(Asrc + abase0 + k0 + kq) : z4;
            a1v = av1 ? *(const float4*)(Asrc + abase1 + k0 + kq) : z4;
            b0v = *(const float4*)(Wsrc + (size_t)(k0 + bkr) * NW + n0 + bc);
            b1v = *(const float4*)(Wsrc + (size_t)(k0 + bkr + 8) * NW + n0 + bc);
        }

        // compute: 16 k-steps, 8x8 per thread via packed f32x2 FMA
#pragma unroll
        for (int k = 0; k < KT; ++k) {
            const float4 af0 = *(const float4*)&sA[k * 128 + ty * 8];
            const float4 af1 = *(const float4*)&sA[k * 128 + ty * 8 + 4];
            const ulonglong2 q0 = *(const ulonglong2*)&sB[k * 128 + tx * 8];
            const ulonglong2 q1 = *(const ulonglong2*)&sB[k * 128 + tx * 8 + 4];
            const uint64_t bb[4] = {q0.x, q0.y, q1.x, q1.y};
            const float af[8] = {af0.x, af0.y, af0.z, af0.w,
                                 af1.x, af1.y, af1.z, af1.w};
#pragma unroll
            for (int i = 0; i < 8; ++i) {
                uint64_t ad;
                asm("mov.b64 %0, {%1, %1};" : "=l"(ad) : "r"(__float_as_uint(af[i])));
#pragma unroll
                for (int p = 0; p < 4; ++p)
                    asm("fma.rn.f32x2 %0, %1, %2, %0;"
                        : "+l"(acc[i][p]) : "l"(ad), "l"(bb[p]));
            }
        }
        __syncthreads();
    }

    // ------------------ epilogue: NA aggregation ------------------
    float* S    = smem;                          // [128][132]
    float* NAs  = S + 128 * 132;                 // [BB][GN][GN]
    float* dinv = NAs + BB * GN * GN;            // [BB*GN]
    float* nws  = dinv + BB * GN;                // [1]

    // spill accumulators to smem (support tile)
#pragma unroll
    for (int i = 0; i < 8; ++i) {
        const int r = ty * 8 + i;
#pragma unroll
        for (int p = 0; p < 4; ++p)
            *(uint64_t*)&S[r * 132 + tx * 8 + 2 * p] = acc[i][p];
    }

    // degree^-1/2 per (batch, node)
    for (int r = tid; r < BB * GN; r += 256) {
        const int b = r / GN, i = r % GN;
        const int batch = batch0 + b;
        float dv = 0.f;
        if (batch < CB) {
            const float* arow = adj + ((size_t)batch * NNODES + GIDX[G][i]) * NNODES;
            float deg = 1.f;   // self loop
#pragma unroll
            for (int j = 0; j < GN; ++j) deg += arow[GIDX[G][j]];
            dv = rsqrtf(deg);
        }
        dinv[r] = dv;
    }
    if (L2 && tid == 0) {
        float w[5];
#pragma unroll
        for (int q = 0; q < 5; ++q) w[q] = fw[q];
        float m = w[0];
#pragma unroll
        for (int q = 1; q < 5; ++q) m = fmaxf(m, w[q]);
        float e[5], s = 0.f;
#pragma unroll
        for (int q = 0; q < 5; ++q) { e[q] = expf(w[q] - m); s += e[q]; }
        nws[0] = e[G] / s;
    }
    __syncthreads();

    // normalized adjacency
    for (int e = tid; e < BB * GN * GN; e += 256) {
        const int b  = e / (GN * GN);
        const int ij = e - b * GN * GN;
        const int i  = ij / GN, j = ij - i * GN;
        const int batch = batch0 + b;
        float v = 0.f;
        if (batch < CB) {
            v = adj[((size_t)batch * NNODES + GIDX[G][i]) * NNODES + GIDX[G][j]];
            if (i == j) v += 1.f;
            v *= dinv[b * GN + i] * dinv[b * GN + j];
        }
        NAs[e] = v;
    }
    __syncthreads();

    const float nw = L2 ? nws[0] : 1.f;

    // aggregate: unit = (row, 8 cols)
    constexpr int NU = MROWS * 16;
    for (int u = tid; u < NU; u += 256) {
        const int r  = u >> 4;
        const int cg = (u & 15) * 8;
        const int b  = r / GN, i = r % GN;
        const int batch = batch0 + b;
        if (batch >= CB) continue;

        float o[8];
#pragma unroll
        for (int q = 0; q < 8; ++q) o[q] = 0.f;
        const float* nrow = &NAs[(b * GN + i) * GN];
        const float* sp   = &S[(b * GN) * 132 + cg];
#pragma unroll
        for (int j = 0; j < GN; ++j) {
            const float na = nrow[j];
            const float4 s0 = *(const float4*)&sp[j * 132];
            const float4 s1 = *(const float4*)&sp[j * 132 + 4];
            o[0] += na * s0.x; o[1] += na * s0.y;
            o[2] += na * s0.z; o[3] += na * s0.w;
            o[4] += na * s1.x; o[5] += na * s1.y;
            o[6] += na * s1.z; o[7] += na * s1.w;
        }
        const float4 bv0 = *(const float4*)&bias[n0 + cg];
        const float4 bv1 = *(const float4*)&bias[n0 + cg + 4];
        o[0] += bv0.x; o[1] += bv0.y; o[2] += bv0.z; o[3] += bv0.w;
        o[4] += bv1.x; o[5] += bv1.y; o[6] += bv1.z; o[7] += bv1.w;
#pragma unroll
        for (int q = 0; q < 8; ++q) o[q] = fmaxf(o[q], 0.f);

        if (!L2) {
            float* dst = hreg + (size_t)(batch * GN + i) * 512 + n0 + cg;
            *(float4*)dst       = make_float4(o[0], o[1], o[2], o[3]);
            *(float4*)(dst + 4) = make_float4(o[4], o[5], o[6], o[7]);
        } else {
            float* dst = dout + ((size_t)batch * NNODES + GIDX[G][i]) * 256 + n0 + cg;
            if (G == 0) {
                *(float4*)dst       = make_float4(o[0]*nw, o[1]*nw, o[2]*nw, o[3]*nw);
                *(float4*)(dst + 4) = make_float4(o[4]*nw, o[5]*nw, o[6]*nw, o[7]*nw);
            } else {
                float4 p0 = *(const float4*)dst;
                float4 p1 = *(const float4*)(dst + 4);
                p0.x += o[0]*nw; p0.y += o[1]*nw; p0.z += o[2]*nw; p0.w += o[3]*nw;
                p1.x += o[4]*nw; p1.y += o[5]*nw; p1.z += o[6]*nw; p1.w += o[7]*nw;
                *(float4*)dst       = p0;
                *(float4*)(dst + 4) = p1;
            }
        }
    }
}

static inline int smem_bytes(int GN, int BB) {
    return (128 * 132 + BB * GN * GN + BB * GN + 8) * 4;
}

extern "C" void kernel_launch(void* const* d_in, const int* in_sizes, int n_in,
                              void* d_out, int out_size) {
    (void)in_sizes; (void)n_in; (void)out_size;
    const float* x   = (const float*)d_in[0];
    const float* adj = (const float*)d_in[1];
    const float* W1  = (const float*)d_in[2];
    const float* b1  = (const float*)d_in[3];
    const float* W2  = (const float*)d_in[4];
    const float* b2  = (const float*)d_in[5];
    const float* fw  = (const float*)d_in[6];
    float* out = (float*)d_out;

#define RUN(G, GN, BB, L2, NTILES)                                              \
    do {                                                                        \
        auto kfn = gcn_kernel<G, GN, BB, L2>;                                   \
        const int smb = smem_bytes(GN, BB);                                     \
        cudaFuncSetAttribute(kfn, cudaFuncAttributeMaxDynamicSharedMemorySize,  \
                             smb);                                              \
        dim3 grid((CB + BB - 1) / BB, NTILES);                                  \
        kfn<<<grid, 256, smb>>>(x, adj, W1, b1, W2, b2, fw, out);               \
    } while (0)

    // layer 1 (independent across groups)
    RUN(0, 25,  5, false, 4);
    RUN(1,  9, 14, false, 4);
    RUN(2,  7, 18, false, 4);
    RUN(3,  6, 21, false, 4);
    RUN(4,  6, 21, false, 4);
    // layer 2: group 0 writes '=', groups 1-4 do ordered RMW '+='
    RUN(0, 25,  5, true, 2);
    RUN(1,  9, 14, true, 2);
    RUN(2,  7, 18, true, 2);
    RUN(3,  6, 21, true, 2);
    RUN(4,  6, 21, true, 2);
#undef RUN
}

// round 3
// speedup vs baseline: 3.5154x; 3.5154x over previous
#include <cuda_runtime.h>
#include <cstdint>
#include <cmath>

#define CB 8192
#define NNODES 25
// group sizes: 25, 9, 7, 6, 6

__constant__ int GIDX[5][25] = {
  {0,1,2,3,4,5,6,7,8,9,10,11,12,13,14,15,16,17,18,19,20,21,22,23,24},
  {0,1,2,3,4,5,6,7,8, 0,0,0,0,0,0,0,0,0,0,0,0,0,0,0,0},
  {0,9,10,11,12,13,14, 0,0,0,0,0,0,0,0,0,0,0,0,0,0,0,0,0,0},
  {6,7,8,12,13,14, 0,0,0,0,0,0,0,0,0,0,0,0,0,0,0,0,0,0,0},
  {3,4,5,9,10,11, 0,0,0,0,0,0,0,0,0,0,0,0,0,0,0,0,0,0,0}
};

// device scratch (no allocations allowed)
__device__ float g_h[(size_t)CB * 53 * 512];     // layer-1 outputs (tf32-rounded)
__device__ float g_xr[(size_t)CB * NNODES * 256]; // tf32-rounded x
__device__ float g_W1r[5 * 256 * 512];            // tf32-rounded W1 [g][k][n]
__device__ float g_W2r[5 * 512 * 256];            // tf32-rounded W2 [g][k][n]

__host__ __device__ constexpr size_t hpre(int g) {
    return g == 0 ? 0 : g == 1 ? 25 : g == 2 ? 34 : g == 3 ? 41 : 47;
}

__device__ __forceinline__ uint32_t smem_u32(const void* p) {
    uint32_t a;
    asm("{ .reg .u64 t; cvta.to.shared.u64 t, %1; cvt.u32.u64 %0, t; }"
        : "=r"(a) : "l"(p));
    return a;
}
__device__ __forceinline__ float tf32r(float v) {
    uint32_t o;
    asm("cvt.rna.tf32.f32 %0, %1;" : "=r"(o) : "f"(v));
    return __uint_as_float(o);
}
__device__ __forceinline__ void cp16(uint32_t dst, const void* src) {
    asm volatile("cp.async.cg.shared.global [%0], [%1], 16;"
                 :: "r"(dst), "l"(src) : "memory");
}
__device__ __forceinline__ void cp_commit() {
    asm volatile("cp.async.commit_group;" ::: "memory");
}
__device__ __forceinline__ void cp_wait1() {
    asm volatile("cp.async.wait_group 1;" ::: "memory");
}
__device__ __forceinline__ void cp_wait0() {
    asm volatile("cp.async.wait_group 0;" ::: "memory");
}
__device__ __forceinline__ void mma_tf32(float* d, const uint32_t* a, const uint32_t* b) {
    asm volatile(
        "mma.sync.aligned.m16n8k8.row.col.f32.tf32.tf32.f32 "
        "{%0,%1,%2,%3}, {%4,%5,%6,%7}, {%8,%9}, {%0,%1,%2,%3};"
        : "+f"(d[0]), "+f"(d[1]), "+f"(d[2]), "+f"(d[3])
        : "r"(a[0]), "r"(a[1]), "r"(a[2]), "r"(a[3]), "r"(b[0]), "r"(b[1]));
}

// ---------------------------------------------------------------------------
// Pre-pass: tf32-round x, W1, W2 into scratch.
// ---------------------------------------------------------------------------
__global__ void round_pre(const float* __restrict__ x,
                          const float* __restrict__ W1,
                          const float* __restrict__ W2) {
    const int t = blockIdx.x * 256 + threadIdx.x;
    constexpr int XN4 = CB * NNODES * 256 / 4;  // 13107200
    constexpr int WN4 = 5 * 256 * 512 / 4;      // 163840
    if (t < XN4) {
        float4 v = ((const float4*)x)[t];
        v.x = tf32r(v.x); v.y = tf32r(v.y); v.z = tf32r(v.z); v.w = tf32r(v.w);
        ((float4*)g_xr)[t] = v;
    }
    if (t < WN4) {
        float4 v = ((const float4*)W1)[t];
        v.x = tf32r(v.x); v.y = tf32r(v.y); v.z = tf32r(v.z); v.w = tf32r(v.w);
        ((float4*)g_W1r)[t] = v;
        v = ((const float4*)W2)[t];
        v.x = tf32r(v.x); v.y = tf32r(v.y); v.z = tf32r(v.z); v.w = tf32r(v.w);
        ((float4*)g_W2r)[t] = v;
    }
}

// ---------------------------------------------------------------------------
// Fused GCN layer, tf32 mma.sync core.
// CTA: 128 rows (BB whole batches) x 128 cols; K in 32-chunks, 2-stage cp.async.
// 8 warps as 2(M) x 4(N); per warp 64x32 via m16n8k8 tiles.
// ---------------------------------------------------------------------------
template<int G, int GN, int BB, bool L2>
__global__ __launch_bounds__(256, 2)
void gcn_mma(const float* __restrict__ adj,
             const float* __restrict__ b1,
             const float* __restrict__ b2,
             const float* __restrict__ fw,
             float* __restrict__ dout)
{
    constexpr int K     = L2 ? 512 : 256;
    constexpr int NW    = L2 ? 256 : 512;
    constexpr int NC    = K / 32;
    constexpr int MROWS = BB * GN;
    constexpr int SA_B  = 128 * 36 * 4;            // 18432
    constexpr int SB_B  = 32 * 136 * 4;            // 17408
    constexpr int STAGE = SA_B + SB_B;             // 35840
    constexpr int NAOFF = 2 * STAGE;               // 71680 bytes

    extern __shared__ char smem[];
    float* smf = (float*)smem;
    const uint32_t sb = smem_u32(smem);

    const int tid  = threadIdx.x;
    const int lane = tid & 31;
    const int wid  = tid >> 5;
    const int warpM = wid >> 2;   // 0..1
    const int warpN = wid & 3;    // 0..3
    const int batch0 = blockIdx.x * BB;
    const int n0     = blockIdx.y * 128;

    float* hreg = g_h + hpre(G) * (size_t)CB * 512;
    const float* Asrc = L2 ? hreg : g_xr;
    const float* Bsrc = L2 ? (g_W2r + (size_t)G * 512 * 256)
                           : (g_W1r + (size_t)G * 256 * 512);
    const float* bias = L2 ? (b2 + G * 256) : (b1 + G * 512);

    // ---- staging issue (c = chunk index, p = buffer) ----
    auto stage = [&](int c, int p) {
#pragma unroll
        for (int i = 0; i < 4; ++i) {
            const int idx = i * 256 + tid;
            // A: 128 rows x 32 k, row-major stride 36 floats
            {
                const int row = idx >> 3, kq = idx & 7;
                const int bq = row / GN;
                const int batch = batch0 + bq;
                const bool valid = (row < MROWS) && (batch < CB);
                const float* src;
                if (L2) src = Asrc + (size_t)(batch0 * GN + row) * 512;
                else    src = Asrc + ((size_t)batch * NNODES +
                                      GIDX[G][row - bq * GN]) * 256;
                if (!valid) src = Asrc;
                src += c * 32 + kq * 4;
                cp16(sb + p * STAGE + row * 144 + kq * 16, src);
            }
            // B: 32 k-rows x 128 n, k-major stride 136 floats
            {
                const int kk = idx >> 5, nq = idx & 31;
                const float* src = Bsrc + (size_t)(c * 32 + kk) * NW + n0 + nq * 4;
                cp16(sb + p * STAGE + SA_B + kk * 544 + nq * 16, src);
            }
        }
    };

    float acc[4][4][4];
#pragma unroll
    for (int mt = 0; mt < 4; ++mt)
#pragma unroll
        for (int nt = 0; nt < 4; ++nt)
#pragma unroll
            for (int r = 0; r < 4; ++r) acc[mt][nt][r] = 0.f;

    stage(0, 0);
    cp_commit();

    // ---- NA precompute (overlaps with first cp.async) ----
    float* NAs  = smf + NAOFF / 4;
    float* dinv = NAs + BB * GN * GN;
    float* nws  = dinv + BB * GN;
    for (int r = tid; r < BB * GN; r += 256) {
        const int b = r / GN, i = r % GN;
        const int batch = batch0 + b;
        float dv = 0.f;
        if (batch < CB) {
            const float* arow = adj + ((size_t)batch * NNODES + GIDX[G][i]) * NNODES;
            float deg = 1.f;
#pragma unroll
            for (int j = 0; j < GN; ++j) deg += arow[GIDX[G][j]];
            dv = rsqrtf(deg);
        }
        dinv[r] = dv;
    }
    if (L2 && tid == 0) {
        float w[5];
#pragma unroll
        for (int q = 0; q < 5; ++q) w[q] = fw[q];
        float m = w[0];
#pragma unroll
        for (int q = 1; q < 5; ++q) m = fmaxf(m, w[q]);
        float e[5], s = 0.f;
#pragma unroll
        for (int q = 0; q < 5; ++q) { e[q] = expf(w[q] - m); s += e[q]; }
        nws[0] = e[G] / s;
    }
    __syncthreads();
    for (int e = tid; e < BB * GN * GN; e += 256) {
        const int b  = e / (GN * GN);
        const int ij = e - b * GN * GN;
        const int i  = ij / GN, j = ij - i * GN;
        const int batch = batch0 + b;
        float v = 0.f;
        if (batch < CB) {
            v = adj[((size_t)batch * NNODES + GIDX[G][i]) * NNODES + GIDX[G][j]];
            if (i == j) v += 1.f;
            v *= dinv[b * GN + i] * dinv[b * GN + j];
        }
        NAs[e] = v;
    }

    // ---- main K loop ----
    const int aRow = warpM * 64 + (lane >> 2);
    const int aCol = lane & 3;
    const int bRow = lane & 3;
    const int bCol = warpN * 32 + (lane >> 2);

    for (int c = 0; c < NC; ++c) {
        const int p = c & 1;
        if (c + 1 < NC) { stage(c + 1, p ^ 1); cp_commit(); cp_wait1(); }
        else            { cp_commit(); cp_wait0(); }
        __syncthreads();

        const uint32_t* sA = (const uint32_t*)(smem + p * STAGE);
        const uint32_t* sB = (const uint32_t*)(smem + p * STAGE + SA_B);
#pragma unroll
        for (int kc = 0; kc < 4; ++kc) {
            uint32_t a[4][4], b[4][2];
#pragma unroll
            for (int mt = 0; mt < 4; ++mt)
#pragma unroll
                for (int r = 0; r < 4; ++r)
                    a[mt][r] = sA[(aRow + mt * 16 + (r & 1) * 8) * 36 +
                                  kc * 8 + aCol + (r >> 1) * 4];
#pragma unroll
            for (int nt = 0; nt < 4; ++nt)
#pragma unroll
                for (int r = 0; r < 2; ++r)
                    b[nt][r] = sB[(bRow + kc * 8 + r * 4) * 136 + bCol + nt * 8];
#pragma unroll
            for (int mt = 0; mt < 4; ++mt)
#pragma unroll
                for (int nt = 0; nt < 4; ++nt)
                    mma_tf32(acc[mt][nt], a[mt], b[nt]);
        }
        __syncthreads();
    }

    // ---- spill accumulators to S[128][132] (aliases staging buffers) ----
    float* S = smf;
#pragma unroll
    for (int mt = 0; mt < 4; ++mt) {
        const int row0 = warpM * 64 + mt * 16 + (lane >> 2);
#pragma unroll
        for (int nt = 0; nt < 4; ++nt) {
            const int col = warpN * 32 + nt * 8 + (lane & 3) * 2;
            *(float2*)&S[row0 * 132 + col]       = make_float2(acc[mt][nt][0], acc[mt][nt][1]);
            *(float2*)&S[(row0 + 8) * 132 + col] = make_float2(acc[mt][nt][2], acc[mt][nt][3]);
        }
    }
    __syncthreads();

    const float nw = L2 ? nws[0] : 1.f;

    // ---- NA aggregation + bias + ReLU + store ----
    constexpr int NU = MROWS * 16;
    for (int u = tid; u < NU; u += 256) {
        const int r  = u >> 4;
        const int cg = (u & 15) * 8;
        const int b  = r / GN, i = r - b * GN;
        const int batch = batch0 + b;
        if (batch >= CB) continue;

        float o[8];
#pragma unroll
        for (int q = 0; q < 8; ++q) o[q] = 0.f;
        const float* nrow = &NAs[(b * GN + i) * GN];
        const float* sp   = &S[(b * GN) * 132 + cg];
#pragma unroll
        for (int j = 0; j < GN; ++j) {
            const float na = nrow[j];
            const float4 s0 = *(const float4*)&sp[j * 132];
            const float4 s1 = *(const float4*)&sp[j * 132 + 4];
            o[0] += na * s0.x; o[1] += na * s0.y;
            o[2] += na * s0.z; o[3] += na * s0.w;
            o[4] += na * s1.x; o[5] += na * s1.y;
            o[6] += na * s1.z; o[7] += na * s1.w;
        }
        const float4 bv0 = *(const float4*)&bias[n0 + cg];
        const float4 bv1 = *(const float4*)&bias[n0 + cg + 4];
        o[0] += bv0.x; o[1] += bv0.y; o[2] += bv0.z; o[3] += bv0.w;
        o[4] += bv1.x; o[5] += bv1.y; o[6] += bv1.z; o[7] += bv1.w;
#pragma unroll
        for (int q = 0; q < 8; ++q) o[q] = fmaxf(o[q], 0.f);

        if (!L2) {
            // round h to tf32 so layer-2 mma sees properly rounded operands
#pragma unroll
            for (int q = 0; q < 8; ++q) o[q] = tf32r(o[q]);
            float* dst = hreg + (size_t)(batch * GN + i) * 512 + n0 + cg;
            *(float4*)dst       = make_float4(o[0], o[1], o[2], o[3]);
            *(float4*)(dst + 4) = make_float4(o[4], o[5], o[6], o[7]);
        } else {
            float* dst = dout + ((size_t)batch * NNODES + GIDX[G][i]) * 256 + n0 + cg;
            if (G == 0) {
                *(float4*)dst       = make_float4(o[0]*nw, o[1]*nw, o[2]*nw, o[3]*nw);
                *(float4*)(dst + 4) = make_float4(o[4]*nw, o[5]*nw, o[6]*nw, o[7]*nw);
            } else {
                float4 p0 = *(const float4*)dst;
                float4 p1 = *(const float4*)(dst + 4);
                p0.x += o[0]*nw; p0.y += o[1]*nw; p0.z += o[2]*nw; p0.w += o[3]*nw;
                p1.x += o[4]*nw; p1.y += o[5]*nw; p1.z += o[6]*nw; p1.w += o[7]*nw;
                *(float4*)dst       = p0;
                *(float4*)(dst + 4) = p1;
            }
        }
    }
}

static inline int smem_total(int GN, int BB) {
    const int NAOFF = 2 * (128 * 36 * 4 + 32 * 136 * 4);
    int b = NAOFF + (BB * GN * GN + BB * GN + 4) * 4;
    return (b + 15) & ~15;
}

extern "C" void kernel_launch(void* const* d_in, const int* in_sizes, int n_in,
                              void* d_out, int out_size) {
    (void)in_sizes; (void)n_in; (void)out_size;
    const float* x   = (const float*)d_in[0];
    const float* adj = (const float*)d_in[1];
    const float* W1  = (const float*)d_in[2];
    const float* b1  = (const float*)d_in[3];
    const float* W2  = (const float*)d_in[4];
    const float* b2  = (const float*)d_in[5];
    const float* fw  = (const float*)d_in[6];
    float* out = (float*)d_out;

    round_pre<<<51200, 256>>>(x, W1, W2);

#define RUN(G, GN, BB, L2, NY)                                                  \
    do {                                                                        \
        auto kfn = gcn_mma<G, GN, BB, L2>;                                      \
        const int smb = smem_total(GN, BB);                                     \
        cudaFuncSetAttribute(kfn, cudaFuncAttributeMaxDynamicSharedMemorySize,  \
                             smb);                                              \
        dim3 grid((CB + BB - 1) / BB, NY);                                      \
        kfn<<<grid, 256, smb>>>(adj, b1, b2, fw, out);                          \
    } while (0)

    // layer 1 (N=512 -> 4 n-tiles)
    RUN(0, 25,  5, false, 4);
    RUN(1,  9, 14, false, 4);
    RUN(2,  7, 18, false, 4);
    RUN(3,  6, 21, false, 4);
    RUN(4,  6, 21, false, 4);
    // layer 2 (N=256 -> 2 n-tiles); group 0 '=', groups 1-4 ordered '+='
    RUN(0, 25,  5, true, 2);
    RUN(1,  9, 14, true, 2);
    RUN(2,  7, 18, true, 2);
    RUN(3,  6, 21, true, 2);
    RUN(4,  6, 21, true, 2);
#undef RUN
}